// round 3
// baseline (speedup 1.0000x reference)
#include <cuda_runtime.h>
#include <cuda_bf16.h>
#include <cuda_fp8.h>
#include <cstdint>
#include <cstddef>

#define DINL __device__ __forceinline__

// ---------------- problem sizes ----------------
#define MM 4096
#define NN 4096
#define KK 4096
#define BLOCKSZ 16

// ---------------- GEMM tiling ----------------
#define BM 128
#define BN 128
#define BK 64            // bf16 elements; 128 bytes per row
#define NKT (KK / BK)    // 64 k-tiles
#define STAGES 3

#define A_BYTES (BM * 128)             // 16 KB
#define B_BYTES (BN * 128)             // 16 KB
#define STAGE_BYTES (A_BYTES + B_BYTES)
#define OFF_A(s) ((s) * STAGE_BYTES)
#define OFF_B(s) (OFF_A(s) + A_BYTES)
#define SMEM_TOTAL (STAGES * STAGE_BYTES)  // 98304 bytes

// scratch (__device__ globals are the sanctioned scratch mechanism)
__device__ __align__(1024) __nv_bfloat16 g_A[(size_t)MM * KK];
__device__ __align__(1024) __nv_bfloat16 g_B[(size_t)NN * KK];

__constant__ float c_tbl[16] = {0.f, 0.5f, 1.f, 1.5f, 2.f, 3.f, 4.f, 6.f,
                                -0.f, -0.5f, -1.f, -1.5f, -2.f, -3.f, -4.f, -6.f};

// ---------------- PTX helpers ----------------
DINL uint32_t smem_u32(const void* p) {
    uint32_t a;
    asm("{ .reg .u64 t; cvta.to.shared.u64 t, %1; cvt.u32.u64 %0, t; }" : "=r"(a) : "l"(p));
    return a;
}

#define SW128(o) ((o) ^ (((o) >> 3) & 0x70))

#define CPA16(dst, src) \
    asm volatile("cp.async.cg.shared.global [%0], [%1], 16;" :: "r"(dst), "l"(src) : "memory")
#define CPA_COMMIT() asm volatile("cp.async.commit_group;" ::: "memory")
#define CPA_WAIT(n)  asm volatile("cp.async.wait_group %0;" :: "n"(n) : "memory")

DINL void ldm_x4(uint32_t* r, uint32_t addr) {
    asm volatile("ldmatrix.sync.aligned.m8n8.x4.shared.b16 {%0,%1,%2,%3}, [%4];"
                 : "=r"(r[0]), "=r"(r[1]), "=r"(r[2]), "=r"(r[3]) : "r"(addr));
}

DINL void mma16816(float* d, const uint32_t* a, const uint32_t* b) {
    asm volatile(
        "mma.sync.aligned.m16n8k16.row.col.f32.bf16.bf16.f32 "
        "{%0,%1,%2,%3}, {%4,%5,%6,%7}, {%8,%9}, {%0,%1,%2,%3};"
        : "+f"(d[0]), "+f"(d[1]), "+f"(d[2]), "+f"(d[3])
        : "r"(a[0]), "r"(a[1]), "r"(a[2]), "r"(a[3]), "r"(b[0]), "r"(b[1]));
}

// ---------------- numeric helpers matching reference ----------------
DINL float fp8_rt(float v) {
    __nv_fp8_storage_t s = __nv_cvt_float_to_fp8(v, __NV_SATFINITE, __NV_E4M3);
    __half_raw hr = __nv_cvt_fp8_to_halfraw(s, __NV_E4M3);
    return __half2float(*reinterpret_cast<__half*>(&hr));
}

// reference e2m1: searchsorted(side='left') over bounds -> midpoints round toward zero
DINL float e2m1_round(float v) {
    float a = fabsf(v);
    float q;
    if (a <= 0.25f)      q = 0.0f;
    else if (a <= 0.75f) q = 0.5f;
    else if (a <= 1.25f) q = 1.0f;
    else if (a <= 1.75f) q = 1.5f;
    else if (a <= 2.5f)  q = 2.0f;
    else if (a <= 3.5f)  q = 3.0f;
    else if (a <= 5.0f)  q = 4.0f;
    else                 q = 6.0f;
    return v < 0.0f ? -q : q;
}

union BF16x16 { __nv_bfloat16 h[16]; uint4 v[2]; };

// ---------------- kernel 1: silu-mul + nvfp4 quant/dequant -> bf16 A ----------------
__global__ void __launch_bounds__(256) act_kernel(const float* __restrict__ x,
                                                  const float* __restrict__ scale) {
    const int m = blockIdx.x;
    const int b = threadIdx.x;  // 16-element block index within the row
    const float4* gx = reinterpret_cast<const float4*>(x + (size_t)m * (2 * KK) + b * 16);
    const float4* ux = reinterpret_cast<const float4*>(x + (size_t)m * (2 * KK) + KK + b * 16);

    float y[16];
#pragma unroll
    for (int i = 0; i < 4; i++) {
        float4 g = gx[i], u = ux[i];
        float gg[4] = {g.x, g.y, g.z, g.w};
        float uu[4] = {u.x, u.y, u.z, u.w};
#pragma unroll
        for (int j = 0; j < 4; j++) {
            float v = gg[j];
            float sig = 1.0f / (1.0f + expf(-v));
            y[i * 4 + j] = v * sig * uu[j];
        }
    }

    float amax = 0.0f;
#pragma unroll
    for (int i = 0; i < 16; i++) amax = fmaxf(amax, fabsf(y[i]));

    const float gs = 1.0f / __ldg(scale);
    const float sf = fp8_rt(amax * (gs * (1.0f / 6.0f)));
    const float inv = (sf > 0.0f) ? (gs / sf) : 0.0f;

    BF16x16 o;
#pragma unroll
    for (int i = 0; i < 16; i++) {
        float v = fminf(6.0f, fmaxf(-6.0f, y[i] * inv));
        o.h[i] = __float2bfloat16(e2m1_round(v) * sf);
    }
    uint4* dst = reinterpret_cast<uint4*>(g_A + (size_t)m * KK + b * 16);
    dst[0] = o.v[0];
    dst[1] = o.v[1];
}

// ---------------- kernel 2: fp4 weight dequant -> bf16 B [N,K] ----------------
__global__ void __launch_bounds__(256) wgt_kernel(const int* __restrict__ w,
                                                  const float* __restrict__ wscale) {
    const int n = blockIdx.x;
    const int b = threadIdx.x;  // 16-k block index (8 packed ints)
    const int4* wp = reinterpret_cast<const int4*>(w + (size_t)n * (KK / 2) + b * 8);
    int4 w0 = wp[0], w1 = wp[1];
    int v[8] = {w0.x, w0.y, w0.z, w0.w, w1.x, w1.y, w1.z, w1.w};
    const float ws = fp8_rt(__ldg(wscale + (size_t)n * (KK / BLOCKSZ) + b));

    BF16x16 o;
#pragma unroll
    for (int i = 0; i < 8; i++) {
        int c = v[i];
        o.h[2 * i]     = __float2bfloat16(c_tbl[c & 15] * ws);        // even k = low nibble
        o.h[2 * i + 1] = __float2bfloat16(c_tbl[(c >> 4) & 15] * ws); // odd k  = high nibble
    }
    uint4* dst = reinterpret_cast<uint4*>(g_B + (size_t)n * KK + b * 16);
    dst[0] = o.v[0];
    dst[1] = o.v[1];
}

// ---------------- kernel 3: pipelined bf16 mma.sync GEMM ----------------
// 8 warps as 2 (m) x 4 (n); warp tile 64 x 32.
__global__ void __launch_bounds__(256, 2)
gemm_kernel(float* __restrict__ out,
            const float* __restrict__ scale,
            const float* __restrict__ wscale2) {
    extern __shared__ char smem[];
    const uint32_t sb = smem_u32(smem);
    const int tid = threadIdx.x;
    const int wid = tid >> 5;
    const int lid = tid & 31;
    const int wm = wid >> 2;      // 0..1
    const int wn = wid & 3;       // 0..3

    const int mBase = blockIdx.y * BM;
    const int nBase = blockIdx.x * BN;

    // per-thread cp.async source/dest precompute: 4 A chunks + 4 B chunks per stage
    const int crow = tid >> 3;        // base row of this thread's chunk group
    const int ccol = tid & 7;         // 16B chunk within row
    // rows covered: crow, crow+32, crow+64, crow+96

    float acc[4][4][4];
#pragma unroll
    for (int mt = 0; mt < 4; mt++)
#pragma unroll
        for (int nt = 0; nt < 4; nt++)
#pragma unroll
            for (int i = 0; i < 4; i++) acc[mt][nt][i] = 0.0f;

    // ---- producer helper (macro to keep registers tight) ----
#define LOAD_STAGE(kt)                                                                   \
    do {                                                                                 \
        const int s_ = (kt) % STAGES;                                                    \
        const int kB_ = (kt) * BK;                                                       \
        const uint32_t ab_ = sb + OFF_A(s_);                                             \
        const uint32_t bb_ = sb + OFF_B(s_);                                             \
        _Pragma("unroll")                                                                \
        for (int i = 0; i < 4; i++) {                                                    \
            int row = crow + i * 32;                                                     \
            CPA16(ab_ + SW128(row * 128 + ccol * 16),                                    \
                  g_A + (size_t)(mBase + row) * KK + kB_ + ccol * 8);                    \
        }                                                                                \
        _Pragma("unroll")                                                                \
        for (int i = 0; i < 4; i++) {                                                    \
            int row = crow + i * 32;                                                     \
            CPA16(bb_ + SW128(row * 128 + ccol * 16),                                    \
                  g_B + (size_t)(nBase + row) * KK + kB_ + ccol * 8);                    \
        }                                                                                \
        CPA_COMMIT();                                                                    \
    } while (0)

    // prologue: fill STAGES-1 stages
#pragma unroll
    for (int kt = 0; kt < STAGES - 1; kt++) LOAD_STAGE(kt);

    // fragment addressing (constant per thread)
    const int lrow = lid & 15;            // ldmatrix row within 16
    const int khalf = (lid >> 4) * 16;    // byte offset of k half

    for (int kt = 0; kt < NKT; kt++) {
        const int s = kt % STAGES;
        CPA_WAIT(STAGES - 2);
        __syncthreads();

        // issue next stage's loads (slot consumed last iteration)
        if (kt + STAGES - 1 < NKT) LOAD_STAGE(kt + STAGES - 1);
        else CPA_COMMIT();  // keep group accounting uniform

        const uint32_t ab = sb + OFF_A(s);
        const uint32_t bb = sb + OFF_B(s);

#pragma unroll
        for (int ks = 0; ks < 4; ks++) {
            const int kb = ks * 32 + khalf;   // byte offset in 128B row
            uint32_t af[4][4];
#pragma unroll
            for (int mt = 0; mt < 4; mt++) {
                int row = wm * 64 + mt * 16 + lrow;
                ldm_x4(af[mt], ab + SW128(row * 128 + kb));
            }
            uint32_t bf0[4], bf1[4];
            {
                int row0 = wn * 32 + lrow;
                int row1 = wn * 32 + 16 + lrow;
                ldm_x4(bf0, bb + SW128(row0 * 128 + kb));
                ldm_x4(bf1, bb + SW128(row1 * 128 + kb));
            }
            uint32_t bp[4][2] = {{bf0[0], bf0[2]}, {bf0[1], bf0[3]},
                                 {bf1[0], bf1[2]}, {bf1[1], bf1[3]}};
#pragma unroll
            for (int mt = 0; mt < 4; mt++)
#pragma unroll
                for (int nt = 0; nt < 4; nt++)
                    mma16816(acc[mt][nt], af[mt], bp[nt]);
        }
        __syncthreads();
    }
#undef LOAD_STAGE

    // ---------------- epilogue ----------------
    const float alpha = __ldg(scale) * __ldg(wscale2);
    const int mrow0 = mBase + wm * 64 + (lid >> 2);
    const int ncol0 = nBase + wn * 32 + (lid & 3) * 2;
#pragma unroll
    for (int mt = 0; mt < 4; mt++) {
#pragma unroll
        for (int nt = 0; nt < 4; nt++) {
            float* p0 = out + (size_t)(mrow0 + mt * 16) * NN + ncol0 + nt * 8;
            float* p1 = out + (size_t)(mrow0 + mt * 16 + 8) * NN + ncol0 + nt * 8;
            float2 v0 = {acc[mt][nt][0] * alpha, acc[mt][nt][1] * alpha};
            float2 v1 = {acc[mt][nt][2] * alpha, acc[mt][nt][3] * alpha};
            *reinterpret_cast<float2*>(p0) = v0;
            *reinterpret_cast<float2*>(p1) = v1;
        }
    }
}

// ---------------- launch ----------------
extern "C" void kernel_launch(void* const* d_in, const int* in_sizes, int n_in,
                              void* d_out, int out_size) {
    const float* x       = (const float*)d_in[0];
    const int*   w       = (const int*)d_in[1];
    const float* wscale  = (const float*)d_in[2];
    const float* wscale2 = (const float*)d_in[3];
    const float* scale   = (const float*)d_in[4];
    float* out = (float*)d_out;

    static bool attr_set = false;
    if (!attr_set) {
        cudaFuncSetAttribute(gemm_kernel, cudaFuncAttributeMaxDynamicSharedMemorySize, SMEM_TOTAL);
        attr_set = true;
    }

    act_kernel<<<MM, 256>>>(x, scale);
    wgt_kernel<<<NN, 256>>>(w, wscale);
    dim3 grid(NN / BN, MM / BM);
    gemm_kernel<<<grid, 256, SMEM_TOTAL>>>(out, scale, wscale2);
}